// round 13
// baseline (speedup 1.0000x reference)
#include <cuda_runtime.h>
#include <cstdint>

typedef unsigned long long u64;

#define N_ACT 80
#define M_CON 85
#define NP1   81
#define PDHG_ITERS 200
#define POWER_ITERS 20

// ---- packed f32x2 helpers ----
static __device__ __forceinline__ u64 pk(float lo, float hi) {
    u64 r; asm("mov.b64 %0, {%1, %2};" : "=l"(r) : "f"(lo), "f"(hi)); return r;
}
static __device__ __forceinline__ float2 up(u64 v) {
    float2 f; asm("mov.b64 {%0, %1}, %2;" : "=f"(f.x), "=f"(f.y) : "l"(v)); return f;
}
static __device__ __forceinline__ u64 ff2(u64 a, u64 b, u64 c) {
    u64 r; asm("fma.rn.f32x2 %0, %1, %2, %3;" : "=l"(r) : "l"(a), "l"(b), "l"(c)); return r;
}
static __device__ __forceinline__ u64 add2(u64 a, u64 b) {
    u64 r; asm("add.rn.f32x2 %0, %1, %2;" : "=l"(r) : "l"(a), "l"(b)); return r;
}

__device__ __forceinline__ float warp_sum(float v) {
    #pragma unroll
    for (int off = 16; off > 0; off >>= 1)
        v += __shfl_xor_sync(0xffffffffu, v, off);
    return v;
}
__device__ __forceinline__ float warp_min(float v) {
    #pragma unroll
    for (int off = 16; off > 0; off >>= 1)
        v = fminf(v, __shfl_xor_sync(0xffffffffu, v, off));
    return v;
}

// Per-group named barrier over 256 threads (warp-aligned groups).
static __device__ __forceinline__ void gsync(int id) {
    asm volatile("bar.sync %0, 256;" :: "r"(id) : "memory");
}

// 44-float packed dot: G[22] (u64 pairs) . V-half (11 ulonglong2 = 44 floats)
__device__ __forceinline__ float dot44(const u64* __restrict__ G,
                                       const ulonglong2* __restrict__ v2) {
    u64 a0 = 0, a1 = 0, a2 = 0, a3 = 0;
    #pragma unroll
    for (int q = 0; q < 10; q += 2) {
        ulonglong2 pa = v2[q];
        ulonglong2 pb = v2[q + 1];
        a0 = ff2(G[2*q + 0], pa.x, a0);
        a1 = ff2(G[2*q + 1], pa.y, a1);
        a2 = ff2(G[2*q + 2], pb.x, a2);
        a3 = ff2(G[2*q + 3], pb.y, a3);
    }
    ulonglong2 pt = v2[10];
    a0 = ff2(G[20], pt.x, a0);
    a1 = ff2(G[21], pt.y, a1);
    u64 s = add2(add2(a0, a1), add2(a2, a3));
    float2 f = up(s);
    return f.x + f.y;
}

// Per-problem shared block; two per CTA (dynamic smem).
// Floats: 5*88 + 8 + 85*81 = 7333; pad[3] -> 7336 floats = 29344 B (16B multiple).
struct GSmem {
    float vec[88];   // v / z_bar (0..80); pads zero
    float y[88];     // Gv / y    (0..84)
    float x0[88];    // x0        (0..79)
    float dv[88];    // x_hat-x0  (0..79)
    float d[88];     // row norms (0..84)
    float red[8];
    float As[M_CON * 81];   // pitch 81
    float pad[3];           // round to 16B multiple
};
static_assert(sizeof(GSmem) % 16 == 0, "GSmem must be 16B multiple for LDS.128");

__global__ __launch_bounds__(512, 1)
void acp_kernel(const float* __restrict__ xhat,
                const float* __restrict__ Aglob,
                const float* __restrict__ bglob,
                float* __restrict__ out,
                int P)
{
    extern __shared__ __align__(16) char smem_raw[];
    GSmem* Gs = reinterpret_cast<GSmem*>(smem_raw);

    const int t    = threadIdx.x;        // 0..511
    const int grp  = t >> 8;             // 0 or 1  (warp-aligned: warps 0-7 / 8-15)
    const int u    = t & 255;            // 0..255 within group
    const int lane = u & 31;
    const int wid  = u >> 5;             // 0..7 within group
    const int part = lane & 1;           // pair = lanes (2k, 2k+1)
    const int idx  = (lane >> 1) * 8 + wid;   // 0..127, interleaved over warps
    const bool rowAct = (idx < M_CON);
    const bool colAct = (idx < NP1);
    const int prob = blockIdx.x * 2 + grp;
    if (prob >= P) return;

    GSmem* H = &Gs[grp];
    const int bid = grp + 1;             // named barrier ids 1,2

    // ---- stage A into shared (coalesced within group) ----
    {
        const float* Ap = Aglob + (size_t)prob * (M_CON * N_ACT);
        for (int i = u; i < M_CON * N_ACT; i += 256) {
            int rr = i / N_ACT;
            int cc = i - rr * N_ACT;
            H->As[rr * 81 + cc] = Ap[i];
        }
    }
    if (u < 88) {
        H->y[u]  = 0.0f;
        H->vec[u] = (u < NP1) ? 1.0f : 0.0f;   // power-iter v0 = ones
        H->x0[u] = 0.0f;
        H->dv[u] = 0.0f;
        H->d[u]  = 0.0f;
    }
    gsync(bid);

    // ---- per-thread packed halves ----
    u64 RP[22];        // row half: part0 = A[idx][0..43]; part1 = A[idx][44..79], slot80=d
    u64 CP[22];        // col half: part p = G[44p .. 44p+43][idx] (zeros past 84)
    float bval = 0.0f;

    #pragma unroll
    for (int k = 0; k < 22; k++) { RP[k] = 0; CP[k] = 0; }

    // row fill + norm (shfl hoisted to warp scope)
    {
        float ss = 0.0f;
        if (rowAct) {
            const float* Ar = &H->As[idx * 81];
            if (part == 0) {
                #pragma unroll
                for (int k = 0; k < 22; k++) {
                    float lo = Ar[2*k], hi = Ar[2*k + 1];
                    RP[k] = pk(lo, hi);
                    ss = fmaf(lo, lo, fmaf(hi, hi, ss));
                }
            } else {
                #pragma unroll
                for (int k = 0; k < 18; k++) {
                    float lo = Ar[44 + 2*k], hi = Ar[45 + 2*k];
                    RP[k] = pk(lo, hi);
                    ss = fmaf(lo, lo, fmaf(hi, hi, ss));
                }
            }
        }
        float tot = ss + __shfl_xor_sync(0xffffffffu, ss, 1);
        if (rowAct) {
            float dval = fmaxf(sqrtf(tot), 1e-12f);
            if (part == 1) RP[18] = pk(dval, 0.0f);   // element 80 of row-G
            if (part == 0) H->d[idx] = dval;
            bval = bglob[(size_t)prob * M_CON + idx];
        }
    }
    gsync(bid);                          // d complete (pads still zero)

    // col fill
    if (colAct) {
        if (idx < N_ACT) {
            if (part == 0) {
                #pragma unroll
                for (int k = 0; k < 22; k++)
                    CP[k] = pk(H->As[(2*k) * 81 + idx], H->As[(2*k + 1) * 81 + idx]);
            } else {
                #pragma unroll
                for (int k = 0; k < 20; k++)
                    CP[k] = pk(H->As[(44 + 2*k) * 81 + idx], H->As[(45 + 2*k) * 81 + idx]);
                CP[20] = pk(H->As[84 * 81 + idx], 0.0f);  // j = 84 (+ zero)
            }
        } else {   // idx == 80: column is d (zero-padded to 88)
            #pragma unroll
            for (int k = 0; k < 22; k++)
                CP[k] = pk(H->d[44 * part + 2*k], H->d[44 * part + 2*k + 1]);
        }
    }

    const ulonglong2* vecV = reinterpret_cast<const ulonglong2*>(H->vec) + 11 * part;
    const ulonglong2* yV   = reinterpret_cast<const ulonglong2*>(H->y)   + 11 * part;

    // ---- power iteration: v <- GT(G v), normalize every 3rd iter + last ----
    for (int pi = 0; pi < POWER_ITERS; pi++) {
        float pr = dot44(RP, vecV);                     // zero for inactive
        float g  = pr + __shfl_xor_sync(0xffffffffu, pr, 1);
        if (rowAct && part == 0) H->y[idx] = g;
        gsync(bid);
        float pc = dot44(CP, yV);
        float w  = pc + __shfl_xor_sync(0xffffffffu, pc, 1);
        const bool norm_now = ((pi % 3) == 2) || (pi == POWER_ITERS - 1);
        if (norm_now) {
            float ss = warp_sum((colAct && part == 0) ? w * w : 0.0f);
            if (lane == 0) H->red[wid] = ss;
            gsync(bid);
            float nrm = sqrtf(((H->red[0] + H->red[1]) + (H->red[2] + H->red[3])) +
                              ((H->red[4] + H->red[5]) + (H->red[6] + H->red[7]))) + 1e-12f;
            if (colAct && part == 0) H->vec[idx] = w / nrm;
        } else {
            if (colAct && part == 0) H->vec[idx] = w;
        }
        gsync(bid);
    }
    // L = ||G v||
    {
        float pr = dot44(RP, vecV);
        float g  = pr + __shfl_xor_sync(0xffffffffu, pr, 1);
        float ss = warp_sum((rowAct && part == 0) ? g * g : 0.0f);
        if (lane == 0) H->red[wid] = ss;
        gsync(bid);
    }
    const float Lnrm = sqrtf(((H->red[0] + H->red[1]) + (H->red[2] + H->red[3])) +
                             ((H->red[4] + H->red[5]) + (H->red[6] + H->red[7])));
    const float tau  = 0.9f / fmaxf(Lnrm, 1e-6f);       // sigma == tau

    // ---- PDHG: 200 fixed iterations ----
    if (u < 88) H->y[u] = 0.0f;
    float zv = 0.0f, yv = 0.0f;
    const float cterm = (idx == N_ACT) ? -1.0f : 0.0f;
    gsync(bid);

    for (int it = 0; it < PDHG_ITERS; it++) {
        float pc  = dot44(CP, yV);
        float gty = pc + __shfl_xor_sync(0xffffffffu, pc, 1);
        float znew = fmaxf(zv - tau * (cterm + gty), 0.0f);
        if (colAct && part == 0) H->vec[idx] = 2.0f * znew - zv;   // z_bar
        zv = znew;
        gsync(bid);
        float pr = dot44(RP, vecV);
        float gz = pr + __shfl_xor_sync(0xffffffffu, pr, 1);
        yv = fmaxf(yv + tau * (gz - bval), 0.0f);
        if (rowAct && part == 0) H->y[idx] = yv;
        gsync(bid);
    }

    // ---- alpha map ----
    if (idx < N_ACT && part == 0) {
        H->x0[idx] = zv;
        H->dv[idx] = xhat[(size_t)prob * N_ACT + idx] - zv;
    }
    gsync(bid);

    const float INF = __int_as_float(0x7f800000);
    float ai;
    {
        // x0/dv pads (incl. slot 80) are zero -> RP's dval term vanishes.
        const ulonglong2* x0V = reinterpret_cast<const ulonglong2*>(H->x0) + 11 * part;
        const ulonglong2* dvV = reinterpret_cast<const ulonglong2*>(H->dv) + 11 * part;
        float p0 = dot44(RP, x0V);
        float p1 = dot44(RP, dvV);
        float ax0 = p0 + __shfl_xor_sync(0xffffffffu, p0, 1);
        float ad  = p1 + __shfl_xor_sync(0xffffffffu, p1, 1);
        if (rowAct) {
            float slack = fmaxf(bval - ax0, 0.0f);
            ai = (ad > 0.0f) ? (slack / (ad + 1e-12f)) : INF;
        } else {
            ai = INF;
        }
    }
    ai = warp_min(ai);
    if (lane == 0) H->red[wid] = ai;
    gsync(bid);
    float alpha = fminf(fminf(fminf(H->red[0], H->red[1]), fminf(H->red[2], H->red[3])),
                        fminf(fminf(H->red[4], H->red[5]), fminf(H->red[6], H->red[7])));
    if (!isfinite(alpha)) alpha = 1.0f;
    alpha = fminf(fmaxf(alpha - 1e-9f, 0.0f), 1.0f);

    if (idx < N_ACT && part == 0)
        out[(size_t)prob * N_ACT + idx] = fmaxf(H->x0[idx] + alpha * H->dv[idx], 0.0f);
}

extern "C" void kernel_launch(void* const* d_in, const int* in_sizes, int n_in,
                              void* d_out, int out_size)
{
    const float* xhat = (const float*)d_in[0];
    const float* A    = (const float*)d_in[1];
    const float* b    = (const float*)d_in[2];
    float* out        = (float*)d_out;
    int P = in_sizes[0] / N_ACT;            // 1024 problems

    size_t smem = 2 * sizeof(GSmem);        // two problems per CTA (~58.7 KB)
    cudaFuncSetAttribute(acp_kernel,
                         cudaFuncAttributeMaxDynamicSharedMemorySize,
                         (int)smem);

    int grid = (P + 1) / 2;                 // 512
    acp_kernel<<<grid, 512, smem>>>(xhat, A, b, out, P);
}